// round 10
// baseline (speedup 1.0000x reference)
#include <cuda_runtime.h>
#include <cstdint>
#include <math.h>

#define NPTS 131072   // B*N
#define NB   65536    // N (points per batch)
#define KNN  32
#define FD   64

typedef unsigned long long u64;

// Scratch (no allocations allowed)
__device__ float g_x1[NPTS * 16];   // 8 MB   lrelu(feat @ Wi^T)
__device__ float g_x2[NPTS * 32];   // 16 MB  [g1 | f1]
__device__ float g_g2[NPTS * 32];   // 16 MB  g2 (lfa2 geo-MLP mean)

// Pre-packed k-pair weights for k_final:
// g_wq[which][dhalf][k2][dloc] = {w[D][2*k2], w[D][2*k2+1]},  D = dhalf*32+dloc
__device__ __align__(16) u64 g_wq[2][2][32][32];

__device__ __forceinline__ float lrelu(float x) { return fmaxf(x, 0.2f * x); }

// ---- packed f32x2 helpers (sm_103a FFMA2 path) ----
__device__ __forceinline__ u64 fma2(u64 a, u64 b, u64 c) {
    u64 r;
    asm("fma.rn.f32x2 %0, %1, %2, %3;" : "=l"(r) : "l"(a), "l"(b), "l"(c));
    return r;
}
__device__ __forceinline__ u64 pk2(float x, float y) {
    u64 r;
    asm("mov.b64 %0, {%1, %2};" : "=l"(r) : "f"(x), "f"(y));
    return r;
}
__device__ __forceinline__ float2 up2(u64 a) {
    float2 v;
    asm("mov.b64 {%0, %1}, %2;" : "=f"(v.x), "=f"(v.y) : "l"(a));
    return v;
}
#define C06_2 0x3F19999A3F19999AULL   // {0.6f, 0.6f}
#define C04_2 0x3ECCCCCD3ECCCCCDULL   // {0.4f, 0.4f}
#define ABSM  0x7FFFFFFF7FFFFFFFULL

// packed lrelu accumulate: acc += lrelu2(s)  where lrelu(x)=0.6x+0.4|x|
__device__ __forceinline__ u64 lrelu_acc2(u64 s, u64 acc) {
    acc = fma2(s, C06_2, acc);
    acc = fma2(s & ABSM, C04_2, acc);
    return acc;
}

__device__ __forceinline__ uint32_t smem_u32(const void* p) {
    uint32_t a;
    asm("{ .reg .u64 t; cvta.to.shared.u64 t, %1; cvt.u32.u64 %0, t; }"
        : "=r"(a) : "l"(p));
    return a;
}
__device__ __forceinline__ void cp16(uint32_t dst, const void* src) {
    asm volatile("cp.async.cg.shared.global [%0], [%1], 16;"
                 :: "r"(dst), "l"(src) : "memory");
}

// ---------------------------------------------------------------------------
// K0: pack w_final / w_res rows into k-pair u64 chunks (one tiny block).
// ---------------------------------------------------------------------------
__global__ __launch_bounds__(256) void k_packw(
    const float* __restrict__ wf, const float* __restrict__ wr)
{
    int t = threadIdx.x;
    u64* dst = &g_wq[0][0][0][0];
#pragma unroll
    for (int e = t; e < 4096; e += 256) {
        int which = e >> 11;
        int rem   = e & 2047;
        int dh    = rem >> 10;
        int k2    = (rem >> 5) & 31;
        int dloc  = rem & 31;
        const float* src = which ? wr : wf;
        dst[e] = *(const u64*)(src + (size_t)(dh * 32 + dloc) * 64 + k2 * 2);
    }
}

// ---------------------------------------------------------------------------
// K1: x1 = lrelu(features @ w_init^T + b_init)   (NPTS, 16)
// ---------------------------------------------------------------------------
__global__ __launch_bounds__(256) void k_init(
    const float* __restrict__ feat, const float* __restrict__ w,
    const float* __restrict__ b)
{
    __shared__ float4 sf4[256];          // 16 points x 64 feats
    __shared__ float  swt[64 * 16];      // transposed w_init
    __shared__ float  sb[16];
    const float* sf = (const float*)sf4;

    int tid = threadIdx.x;
    int fb  = blockIdx.x * 16;

    const float4* f4 = (const float4*)feat + (size_t)fb * 16;
    sf4[tid] = f4[tid];

#pragma unroll
    for (int e = tid; e < 1024; e += 256) {
        int d = e >> 6, i = e & 63;
        swt[i * 16 + d] = w[e];
    }
    if (tid < 16) sb[tid] = b[tid];
    __syncthreads();

    int p = tid >> 4, d = tid & 15;
    float acc = sb[d];
#pragma unroll
    for (int i = 0; i < 64; i++)
        acc = fmaf(sf[p * 64 + i], swt[i * 16 + d], acc);

    g_x1[(size_t)fb * 16 + tid] = lrelu(acc);
}

// ---------------------------------------------------------------------------
// K2: fused geo-MLPs of lfa1 + lfa2 (shared geometry) + x1 gather-mean.
// One warp per point. Geo staged SoA in SMEM; packed f32x2 over neighbor pairs.
//   g2 -> g_g2[r][0:32],  g1 -> g_x2[r][0:16],  f1 -> g_x2[r][16:32]
// ---------------------------------------------------------------------------
__global__ __launch_bounds__(256) void k_lfa_geo(
    const float* __restrict__ pts, const int* __restrict__ idx,
    const float* __restrict__ w1, const float* __restrict__ b1,
    const float* __restrict__ w2, const float* __restrict__ b2)
{
    __shared__ __align__(16) float sgx[8][32];
    __shared__ __align__(16) float sgy[8][32];
    __shared__ __align__(16) float sgz[8][32];
    __shared__ __align__(16) float sgd[8][32];
    __shared__ int sidx[8][32];

    int lane = threadIdx.x & 31;
    int wid  = threadIdx.x >> 5;
    int r    = blockIdx.x * 8 + wid;
    int base = (r >= NB) ? NB : 0;       // batch row base

    int ij = idx[(size_t)r * KNN + lane];
    sidx[wid][lane] = ij;

    float cx = pts[(size_t)r * 3 + 0];
    float cy = pts[(size_t)r * 3 + 1];
    float cz = pts[(size_t)r * 3 + 2];

    size_t gr = (size_t)(base + ij) * 3;
    float px = pts[gr + 0], py = pts[gr + 1], pz = pts[gr + 2];

    float rx = cx - px, ry = cy - py, rz = cz - pz;
    float dist = sqrtf(fmaf(rx, rx, fmaf(ry, ry, rz * rz)));
    sgx[wid][lane] = rx;
    sgy[wid][lane] = ry;
    sgz[wid][lane] = rz;
    sgd[wid][lane] = dist;

    // per-lane weight rows, packed {w,w}
    float4 w2r = ((const float4*)w2)[lane];
    u64 w2xx = pk2(w2r.x, w2r.x), w2yy = pk2(w2r.y, w2r.y);
    u64 w2zz = pk2(w2r.z, w2r.z), w2ww = pk2(w2r.w, w2r.w);
    u64 bias2 = pk2(b2[lane], b2[lane]);

    int dlo = lane & 15;
    int h   = lane >> 4;
    float4 w1r = ((const float4*)w1)[dlo];
    u64 w1xx = pk2(w1r.x, w1r.x), w1yy = pk2(w1r.y, w1r.y);
    u64 w1zz = pk2(w1r.z, w1r.z), w1ww = pk2(w1r.w, w1r.w);
    u64 bias1 = pk2(b1[dlo], b1[dlo]);

    __syncwarp();

    u64 ag2 = 0, ag1 = 0;
    float af1 = 0.f;

#pragma unroll
    for (int it = 0; it < 8; it++) {
        int j0 = it * 4;
        // LDS.128 broadcast: two packed neighbor-pairs per component
        ulonglong2 gx = *(const ulonglong2*)&sgx[wid][j0];
        ulonglong2 gy = *(const ulonglong2*)&sgy[wid][j0];
        ulonglong2 gz = *(const ulonglong2*)&sgz[wid][j0];
        ulonglong2 gd = *(const ulonglong2*)&sgd[wid][j0];

        // ---- g2: all 32 lanes (d = lane), both pairs ----
        u64 s0 = fma2(gx.x, w2xx, bias2);
        s0 = fma2(gy.x, w2yy, s0);
        s0 = fma2(gz.x, w2zz, s0);
        s0 = fma2(gd.x, w2ww, s0);
        ag2 = lrelu_acc2(s0, ag2);

        u64 s1 = fma2(gx.y, w2xx, bias2);
        s1 = fma2(gy.y, w2yy, s1);
        s1 = fma2(gz.y, w2zz, s1);
        s1 = fma2(gd.y, w2ww, s1);
        ag2 = lrelu_acc2(s1, ag2);

        // ---- g1: lanes<16 take pair0, lanes>=16 take pair1 (dims dlo) ----
        u64 qx = h ? gx.y : gx.x;
        u64 qy = h ? gy.y : gy.x;
        u64 qz = h ? gz.y : gz.x;
        u64 qd = h ? gd.y : gd.x;
        u64 t = fma2(qx, w1xx, bias1);
        t = fma2(qy, w1yy, t);
        t = fma2(qz, w1zz, t);
        t = fma2(qd, w1ww, t);
        ag1 = lrelu_acc2(t, ag1);

        // ---- f1 gather: lanes<16 rows j0,j0+1; lanes>=16 rows j0+2,j0+3 ----
        int jb = j0 + 2 * h;
        int n0 = sidx[wid][jb];
        int n1 = sidx[wid][jb + 1];
        af1 += g_x1[(size_t)(base + n0) * 16 + dlo];
        af1 += g_x1[(size_t)(base + n1) * 16 + dlo];
    }

    const float inv = 1.0f / 32.0f;

    float2 a2 = up2(ag2);
    g_g2[(size_t)r * 32 + lane] = (a2.x + a2.y) * inv;

    // fold lane-halves for g1 / f1
    u64 ag1o = __shfl_down_sync(0xffffffffu, ag1, 16);
    float af1o = __shfl_down_sync(0xffffffffu, af1, 16);
    if (lane < 16) {
        float2 a1  = up2(ag1);
        float2 a1o = up2(ag1o);
        g_x2[(size_t)r * 32 + lane]      = (a1.x + a1.y + a1o.x + a1o.y) * inv;
        g_x2[(size_t)r * 32 + 16 + lane] = (af1 + af1o) * inv;
    }
}

// ---------------------------------------------------------------------------
// K3 (fused): f2 gather + both GEMMs + residual + output.
//   x3[p] = [g2[p] (cp.async) | mean_k x2[nbr] (warp gather)]
//   out   = lrelu(x3 @ wf^T + bf) + lrelu(feat @ wr^T + br)
// 256 thr, 128-pt tile, both out-halves via two register-reusing passes.
// The L2-cap gather overlaps other blocks' FFMA2 GEMM work chip-wide.
// ---------------------------------------------------------------------------
__global__ __launch_bounds__(256) void k_final_fused(
    const int* __restrict__ idx, const float* __restrict__ feat,
    const float* __restrict__ bf, const float* __restrict__ br,
    float* __restrict__ out)
{
    __shared__ float4 sxA[128 * 17];            // x3 tile: [g2 | f2], padded
    __shared__ float4 sxB[128 * 17];            // feat tile, padded

    int tid  = threadIdx.x;
    int r0   = blockIdx.x * 128;
    int base = (r0 >= NB) ? NB : 0;             // whole tile in one batch
    int lane = tid & 31;
    int w8   = tid >> 5;                        // warp 0..7

    // ---- stream g2 (x3 cols 0..31) and feat tile via cp.async ----
    {
        uint32_t sA = smem_u32(sxA);
        uint32_t sB = smem_u32(sxB);
        const float4* srcA = (const float4*)g_g2 + (size_t)r0 * 8;
        const float4* srcB = (const float4*)feat + (size_t)r0 * 16;
#pragma unroll
        for (int e = tid; e < 1024; e += 256) {
            int p = e >> 3, k4 = e & 7;
            cp16(sA + (uint32_t)(p * 17 + k4) * 16, srcA + e);
        }
#pragma unroll
        for (int e = tid; e < 2048; e += 256) {
            int p = e >> 4, k4 = e & 15;
            cp16(sB + (uint32_t)(p * 17 + k4) * 16, srcB + e);
        }
        asm volatile("cp.async.commit_group;" ::: "memory");
    }

    // ---- f2 gather: warp-per-point, 16 pts/warp, lane = dim ----
    {
        float* sxf = (float*)sxA;
        const float inv = 1.0f / 32.0f;
#pragma unroll
        for (int t = 0; t < 16; t++) {
            int p = w8 * 16 + t;
            int nj = idx[(size_t)(r0 + p) * KNN + lane];   // coalesced
            float acc = 0.f;
#pragma unroll
            for (int j = 0; j < 32; j++) {
                int nr = __shfl_sync(0xffffffffu, nj, j);
                acc += g_x2[(size_t)(base + nr) * 32 + lane];  // 128B coalesced
            }
            sxf[p * 68 + 32 + lane] = acc * inv;           // x3 cols 32..63
        }
    }

    asm volatile("cp.async.wait_group 0;" ::: "memory");
    __syncthreads();

    // ---- GEMM passes: c = out group (0..7 -> 4 outs), rw = 0..31 ----
    int c    = tid & 7;
    int rw   = tid >> 3;                        // points p = rw + 32*i
    int dloc = c * 4;
    float4* out4 = (float4*)out;

    for (int dh = 0; dh < 2; dh++) {
        u64 acc[4][4];
        float po[4][4];

        // ---- phase A: x3 @ wf^T ----
#pragma unroll
        for (int i = 0; i < 4; i++)
#pragma unroll
            for (int j = 0; j < 4; j++) acc[i][j] = 0ull;

#pragma unroll
        for (int k4 = 0; k4 < 16; k4++) {
            const ulonglong2* wpA = (const ulonglong2*)&g_wq[0][dh][2 * k4][dloc];
            const ulonglong2* wpB = (const ulonglong2*)&g_wq[0][dh][2 * k4 + 1][dloc];
            ulonglong2 wv0 = wpA[0], wv1 = wpA[1];
            ulonglong2 wv2 = wpB[0], wv3 = wpB[1];
#pragma unroll
            for (int i = 0; i < 4; i++) {
                ulonglong2 xv = *(const ulonglong2*)&sxA[(rw + 32 * i) * 17 + k4];
                acc[i][0] = fma2(xv.x, wv0.x, acc[i][0]);
                acc[i][0] = fma2(xv.y, wv2.x, acc[i][0]);
                acc[i][1] = fma2(xv.x, wv0.y, acc[i][1]);
                acc[i][1] = fma2(xv.y, wv2.y, acc[i][1]);
                acc[i][2] = fma2(xv.x, wv1.x, acc[i][2]);
                acc[i][2] = fma2(xv.y, wv3.x, acc[i][2]);
                acc[i][3] = fma2(xv.x, wv1.y, acc[i][3]);
                acc[i][3] = fma2(xv.y, wv3.y, acc[i][3]);
            }
        }
        {
            float4 bv = *(const float4*)(bf + dh * 32 + dloc);
#pragma unroll
            for (int i = 0; i < 4; i++)
#pragma unroll
                for (int j = 0; j < 4; j++) {
                    float2 v = up2(acc[i][j]);
                    po[i][j] = lrelu(v.x + v.y + (&bv.x)[j]);
                }
        }

        // ---- phase B: feat @ wr^T ----
#pragma unroll
        for (int i = 0; i < 4; i++)
#pragma unroll
            for (int j = 0; j < 4; j++) acc[i][j] = 0ull;

#pragma unroll
        for (int k4 = 0; k4 < 16; k4++) {
            const ulonglong2* wpA = (const ulonglong2*)&g_wq[1][dh][2 * k4][dloc];
            const ulonglong2* wpB = (const ulonglong2*)&g_wq[1][dh][2 * k4 + 1][dloc];
            ulonglong2 wv0 = wpA[0], wv1 = wpA[1];
            ulonglong2 wv2 = wpB[0], wv3 = wpB[1];
#pragma unroll
            for (int i = 0; i < 4; i++) {
                ulonglong2 xv = *(const ulonglong2*)&sxB[(rw + 32 * i) * 17 + k4];
                acc[i][0] = fma2(xv.x, wv0.x, acc[i][0]);
                acc[i][0] = fma2(xv.y, wv2.x, acc[i][0]);
                acc[i][1] = fma2(xv.x, wv0.y, acc[i][1]);
                acc[i][1] = fma2(xv.y, wv2.y, acc[i][1]);
                acc[i][2] = fma2(xv.x, wv1.x, acc[i][2]);
                acc[i][2] = fma2(xv.y, wv3.x, acc[i][2]);
                acc[i][3] = fma2(xv.x, wv1.y, acc[i][3]);
                acc[i][3] = fma2(xv.y, wv3.y, acc[i][3]);
            }
        }

        // combine + store (float4 per point)
        float4 bv2 = *(const float4*)(br + dh * 32 + dloc);
#pragma unroll
        for (int i = 0; i < 4; i++) {
            int p = rw + 32 * i;
            float4 v;
#pragma unroll
            for (int j = 0; j < 4; j++) {
                float2 w2 = up2(acc[i][j]);
                (&v.x)[j] = po[i][j] + lrelu(w2.x + w2.y + (&bv2.x)[j]);
            }
            out4[(size_t)(r0 + p) * 16 + dh * 8 + c] = v;
        }
    }
}

// ---------------------------------------------------------------------------
extern "C" void kernel_launch(void* const* d_in, const int* in_sizes, int n_in,
                              void* d_out, int out_size)
{
    const float* points  = (const float*)d_in[0];
    const float* feats   = (const float*)d_in[1];
    const int*   idx     = (const int*)d_in[2];
    const float* w_init  = (const float*)d_in[3];
    const float* b_init  = (const float*)d_in[4];
    const float* w_lfa1  = (const float*)d_in[5];
    const float* b_lfa1  = (const float*)d_in[6];
    const float* w_lfa2  = (const float*)d_in[7];
    const float* b_lfa2  = (const float*)d_in[8];
    const float* w_final = (const float*)d_in[9];
    const float* b_final = (const float*)d_in[10];
    const float* w_res   = (const float*)d_in[11];
    const float* b_res   = (const float*)d_in[12];
    float* out = (float*)d_out;

    k_packw<<<1, 256>>>(w_final, w_res);
    k_init<<<NPTS / 16, 256>>>(feats, w_init, b_init);
    k_lfa_geo<<<NPTS / 8, 256>>>(points, idx, w_lfa1, b_lfa1, w_lfa2, b_lfa2);
    k_final_fused<<<NPTS / 128, 256>>>(idx, feats, b_final, b_res, out);
}

// round 11
// speedup vs baseline: 1.2044x; 1.2044x over previous
#include <cuda_runtime.h>
#include <cstdint>
#include <math.h>

#define NPTS 131072   // B*N
#define NB   65536    // N (points per batch)
#define KNN  32
#define FD   64

typedef unsigned long long u64;

// Scratch (no allocations allowed)
__device__ float g_x1[NPTS * 16];   // 8 MB   lrelu(feat @ Wi^T)
__device__ float g_x2[NPTS * 32];   // 16 MB  [g1 | f1]
__device__ float g_x3[NPTS * 64];   // 32 MB  [g2 | f2]
__device__ float4 g_pts4[NPTS];     // 2 MB   padded points (x,y,z,0)

// Pre-packed k-pair weights for k_final:
// g_wq[which][dhalf][k2][dloc] = {w[D][2*k2], w[D][2*k2+1]},  D = dhalf*32+dloc
__device__ __align__(16) u64 g_wq[2][2][32][32];

__device__ __forceinline__ float lrelu(float x) { return fmaxf(x, 0.2f * x); }

// ---- packed f32x2 helpers (sm_103a FFMA2 path) ----
__device__ __forceinline__ u64 fma2(u64 a, u64 b, u64 c) {
    u64 r;
    asm("fma.rn.f32x2 %0, %1, %2, %3;" : "=l"(r) : "l"(a), "l"(b), "l"(c));
    return r;
}
__device__ __forceinline__ u64 pk2(float x, float y) {
    u64 r;
    asm("mov.b64 %0, {%1, %2};" : "=l"(r) : "f"(x), "f"(y));
    return r;
}
__device__ __forceinline__ float2 up2(u64 a) {
    float2 v;
    asm("mov.b64 {%0, %1}, %2;" : "=f"(v.x), "=f"(v.y) : "l"(a));
    return v;
}
#define C06_2 0x3F19999A3F19999AULL   // {0.6f, 0.6f}
#define C04_2 0x3ECCCCCD3ECCCCCDULL   // {0.4f, 0.4f}
#define ABSM  0x7FFFFFFF7FFFFFFFULL

// packed lrelu accumulate: acc += lrelu2(s)  where lrelu(x)=0.6x+0.4|x|
__device__ __forceinline__ u64 lrelu_acc2(u64 s, u64 acc) {
    acc = fma2(s, C06_2, acc);
    acc = fma2(s & ABSM, C04_2, acc);
    return acc;
}

__device__ __forceinline__ uint32_t smem_u32(const void* p) {
    uint32_t a;
    asm("{ .reg .u64 t; cvta.to.shared.u64 t, %1; cvt.u32.u64 %0, t; }"
        : "=r"(a) : "l"(p));
    return a;
}
__device__ __forceinline__ void cp16(uint32_t dst, const void* src) {
    asm volatile("cp.async.cg.shared.global [%0], [%1], 16;"
                 :: "r"(dst), "l"(src) : "memory");
}

// ---------------------------------------------------------------------------
// K0a: pack w_final / w_res rows into k-pair u64 chunks (one tiny block).
// ---------------------------------------------------------------------------
__global__ __launch_bounds__(256) void k_packw(
    const float* __restrict__ wf, const float* __restrict__ wr)
{
    int t = threadIdx.x;
    u64* dst = &g_wq[0][0][0][0];
#pragma unroll
    for (int e = t; e < 4096; e += 256) {
        int which = e >> 11;
        int rem   = e & 2047;
        int dh    = rem >> 10;
        int k2    = (rem >> 5) & 31;
        int dloc  = rem & 31;
        const float* src = which ? wr : wf;
        dst[e] = *(const u64*)(src + (size_t)(dh * 32 + dloc) * 64 + k2 * 2);
    }
}

// ---------------------------------------------------------------------------
// K0b: pad points (B,N,3) -> float4 (x,y,z,0) so neighbor gathers are one
// LDG.128 instead of three scattered scalar LDGs.
// ---------------------------------------------------------------------------
__global__ __launch_bounds__(256) void k_prep_pts(const float* __restrict__ pts)
{
    int i = blockIdx.x * 256 + threadIdx.x;
    size_t b = (size_t)i * 3;
    g_pts4[i] = make_float4(pts[b], pts[b + 1], pts[b + 2], 0.f);
}

// ---------------------------------------------------------------------------
// K1: x1 = lrelu(features @ w_init^T + b_init)   (NPTS, 16)
// ---------------------------------------------------------------------------
__global__ __launch_bounds__(256) void k_init(
    const float* __restrict__ feat, const float* __restrict__ w,
    const float* __restrict__ b)
{
    __shared__ float4 sf4[256];          // 16 points x 64 feats
    __shared__ float  swt[64 * 16];      // transposed w_init
    __shared__ float  sb[16];
    const float* sf = (const float*)sf4;

    int tid = threadIdx.x;
    int fb  = blockIdx.x * 16;

    const float4* f4 = (const float4*)feat + (size_t)fb * 16;
    sf4[tid] = f4[tid];

#pragma unroll
    for (int e = tid; e < 1024; e += 256) {
        int d = e >> 6, i = e & 63;
        swt[i * 16 + d] = w[e];
    }
    if (tid < 16) sb[tid] = b[tid];
    __syncthreads();

    int p = tid >> 4, d = tid & 15;
    float acc = sb[d];
#pragma unroll
    for (int i = 0; i < 64; i++)
        acc = fmaf(sf[p * 64 + i], swt[i * 16 + d], acc);

    g_x1[(size_t)fb * 16 + tid] = lrelu(acc);
}

// ---------------------------------------------------------------------------
// K2: fused geo-MLPs of lfa1 + lfa2 (shared geometry) + x1 gather-mean.
// One warp per point. Neighbor points via single LDG.128 from g_pts4.
// Dual accumulator chains halve the dependent-FMA2 latency.
// ---------------------------------------------------------------------------
__global__ __launch_bounds__(256) void k_lfa_geo(
    const int* __restrict__ idx,
    const float* __restrict__ w1, const float* __restrict__ b1,
    const float* __restrict__ w2, const float* __restrict__ b2)
{
    __shared__ __align__(16) float sgx[8][32];
    __shared__ __align__(16) float sgy[8][32];
    __shared__ __align__(16) float sgz[8][32];
    __shared__ __align__(16) float sgd[8][32];
    __shared__ int sidx[8][32];

    int lane = threadIdx.x & 31;
    int wid  = threadIdx.x >> 5;
    int r    = blockIdx.x * 8 + wid;
    int base = (r >= NB) ? NB : 0;       // batch row base

    int ij = idx[(size_t)r * KNN + lane];
    sidx[wid][lane] = ij;

    float4 cp = g_pts4[r];                       // broadcast LDG.128
    float4 np = g_pts4[base + ij];               // scattered LDG.128

    float rx = cp.x - np.x, ry = cp.y - np.y, rz = cp.z - np.z;
    float dist = sqrtf(fmaf(rx, rx, fmaf(ry, ry, rz * rz)));
    sgx[wid][lane] = rx;
    sgy[wid][lane] = ry;
    sgz[wid][lane] = rz;
    sgd[wid][lane] = dist;

    // per-lane weight rows, packed {w,w}
    float4 w2r = ((const float4*)w2)[lane];
    u64 w2xx = pk2(w2r.x, w2r.x), w2yy = pk2(w2r.y, w2r.y);
    u64 w2zz = pk2(w2r.z, w2r.z), w2ww = pk2(w2r.w, w2r.w);
    u64 bias2 = pk2(b2[lane], b2[lane]);

    int dlo = lane & 15;
    int h   = lane >> 4;
    float4 w1r = ((const float4*)w1)[dlo];
    u64 w1xx = pk2(w1r.x, w1r.x), w1yy = pk2(w1r.y, w1r.y);
    u64 w1zz = pk2(w1r.z, w1r.z), w1ww = pk2(w1r.w, w1r.w);
    u64 bias1 = pk2(b1[dlo], b1[dlo]);

    __syncwarp();

    u64 ag2a = 0, ag2b = 0, ag1a = 0, ag1b = 0;
    float af1 = 0.f;

#pragma unroll
    for (int it = 0; it < 8; it++) {
        int j0 = it * 4;
        // LDS.128 broadcast: two packed neighbor-pairs per component
        ulonglong2 gx = *(const ulonglong2*)&sgx[wid][j0];
        ulonglong2 gy = *(const ulonglong2*)&sgy[wid][j0];
        ulonglong2 gz = *(const ulonglong2*)&sgz[wid][j0];
        ulonglong2 gd = *(const ulonglong2*)&sgd[wid][j0];

        // ---- g2: all 32 lanes (d = lane), both pairs (dual chains) ----
        u64 s0 = fma2(gx.x, w2xx, bias2);
        s0 = fma2(gy.x, w2yy, s0);
        s0 = fma2(gz.x, w2zz, s0);
        s0 = fma2(gd.x, w2ww, s0);
        ag2a = lrelu_acc2(s0, ag2a);

        u64 s1 = fma2(gx.y, w2xx, bias2);
        s1 = fma2(gy.y, w2yy, s1);
        s1 = fma2(gz.y, w2zz, s1);
        s1 = fma2(gd.y, w2ww, s1);
        ag2b = lrelu_acc2(s1, ag2b);

        // ---- g1: lanes<16 take pair0, lanes>=16 take pair1 (dims dlo) ----
        u64 qx = h ? gx.y : gx.x;
        u64 qy = h ? gy.y : gy.x;
        u64 qz = h ? gz.y : gz.x;
        u64 qd = h ? gd.y : gd.x;
        u64 t = fma2(qx, w1xx, bias1);
        t = fma2(qy, w1yy, t);
        t = fma2(qz, w1zz, t);
        t = fma2(qd, w1ww, t);
        if (it & 1) ag1b = lrelu_acc2(t, ag1b);
        else        ag1a = lrelu_acc2(t, ag1a);

        // ---- f1 gather: lanes<16 rows j0,j0+1; lanes>=16 rows j0+2,j0+3 ----
        int jb = j0 + 2 * h;
        int n0 = sidx[wid][jb];
        int n1 = sidx[wid][jb + 1];
        af1 += g_x1[(size_t)(base + n0) * 16 + dlo];
        af1 += g_x1[(size_t)(base + n1) * 16 + dlo];
    }

    const float inv = 1.0f / 32.0f;

    float2 a2a = up2(ag2a);
    float2 a2b = up2(ag2b);
    g_x3[(size_t)r * 64 + lane] = (a2a.x + a2a.y + a2b.x + a2b.y) * inv;

    // fold lane-halves for g1 / f1
    u64 ag1 = 0;
    {
        float2 pa = up2(ag1a), pb = up2(ag1b);
        ag1 = pk2(pa.x + pb.x, pa.y + pb.y);
    }
    u64 ag1o = __shfl_down_sync(0xffffffffu, ag1, 16);
    float af1o = __shfl_down_sync(0xffffffffu, af1, 16);
    if (lane < 16) {
        float2 a1  = up2(ag1);
        float2 a1o = up2(ag1o);
        g_x2[(size_t)r * 32 + lane]      = (a1.x + a1.y + a1o.x + a1o.y) * inv;
        g_x2[(size_t)r * 32 + 16 + lane] = (af1 + af1o) * inv;
    }
}

// ---------------------------------------------------------------------------
// K3a: f2[d] = mean_k x2[nbr_k][d]  (32 dims)  -> g_x3[r][32:64]
// At the LTS chip throughput cap (~11 TB/s of L2 gather) — do not touch.
// ---------------------------------------------------------------------------
__global__ __launch_bounds__(256) void k_gather2(const int* __restrict__ idx)
{
    __shared__ int sidx[8][32];
    int lane = threadIdx.x & 31;
    int wid  = threadIdx.x >> 5;
    int r    = blockIdx.x * 8 + wid;
    int base = (r >= NB) ? NB : 0;

    sidx[wid][lane] = idx[(size_t)r * KNN + lane];
    __syncwarp();

    float acc = 0.f;
#pragma unroll
    for (int j = 0; j < 32; j++) {
        int nr = sidx[wid][j];
        acc += g_x2[(size_t)(base + nr) * 32 + lane];  // coalesced 128B
    }
    g_x3[(size_t)r * 64 + 32 + lane] = acc * (1.0f / 32.0f);
}

// ---------------------------------------------------------------------------
// K3b: out = lrelu(x3 @ wf^T + bf) + lrelu(feat @ wr^T + br)
// Two-phase, cp.async double-buffered: both tiles stream in up front; phase-B
// fill overlaps phase-A compute. w via L1-resident LDG.128 from g_wq,
// packed FFMA2, zero packing movs. 128 thr, 8 pts x 4 outs.
// ---------------------------------------------------------------------------
__global__ __launch_bounds__(128) void k_final(
    const float* __restrict__ feat,
    const float* __restrict__ bf, const float* __restrict__ br,
    float* __restrict__ out)
{
    __shared__ float4 sxA[128 * 17];            // x3 tile, padded
    __shared__ float4 sxB[128 * 17];            // feat tile, padded

    int tid   = threadIdx.x;
    int dhalf = blockIdx.y;                     // 0: outs 0-31, 1: outs 32-63
    int r0    = blockIdx.x * 128;
    int c     = tid & 7;                        // out group: local d = c*4..c*4+3
    int rw    = tid >> 3;                       // 0..15; points p = rw + 16*i
    int dloc  = c * 4;

    // ---- stream both tiles in via cp.async (B overlaps A's compute) ----
    {
        uint32_t sA = smem_u32(sxA);
        uint32_t sB = smem_u32(sxB);
        const float4* srcA = (const float4*)g_x3 + (size_t)r0 * 16;
        const float4* srcB = (const float4*)feat + (size_t)r0 * 16;
#pragma unroll
        for (int e = tid; e < 2048; e += 128) {
            int p = e >> 4, k4 = e & 15;
            cp16(sA + (uint32_t)(p * 17 + k4) * 16, srcA + e);
        }
        asm volatile("cp.async.commit_group;" ::: "memory");
#pragma unroll
        for (int e = tid; e < 2048; e += 128) {
            int p = e >> 4, k4 = e & 15;
            cp16(sB + (uint32_t)(p * 17 + k4) * 16, srcB + e);
        }
        asm volatile("cp.async.commit_group;" ::: "memory");
    }

    u64 acc[8][4];
    float po[8][4];

    // ================ phase A: x3 @ wf^T ================
    asm volatile("cp.async.wait_group 1;" ::: "memory");
    __syncthreads();

#pragma unroll
    for (int i = 0; i < 8; i++)
#pragma unroll
        for (int j = 0; j < 4; j++) acc[i][j] = 0ull;

#pragma unroll
    for (int k4 = 0; k4 < 16; k4++) {
        const ulonglong2* wpA = (const ulonglong2*)&g_wq[0][dhalf][2 * k4][dloc];
        const ulonglong2* wpB = (const ulonglong2*)&g_wq[0][dhalf][2 * k4 + 1][dloc];
        ulonglong2 wv0 = wpA[0], wv1 = wpA[1];
        ulonglong2 wv2 = wpB[0], wv3 = wpB[1];
#pragma unroll
        for (int i = 0; i < 8; i++) {
            ulonglong2 xv = *(const ulonglong2*)&sxA[(rw + 16 * i) * 17 + k4];
            acc[i][0] = fma2(xv.x, wv0.x, acc[i][0]);
            acc[i][0] = fma2(xv.y, wv2.x, acc[i][0]);
            acc[i][1] = fma2(xv.x, wv0.y, acc[i][1]);
            acc[i][1] = fma2(xv.y, wv2.y, acc[i][1]);
            acc[i][2] = fma2(xv.x, wv1.x, acc[i][2]);
            acc[i][2] = fma2(xv.y, wv3.x, acc[i][2]);
            acc[i][3] = fma2(xv.x, wv1.y, acc[i][3]);
            acc[i][3] = fma2(xv.y, wv3.y, acc[i][3]);
        }
    }

    {
        float4 bv = *(const float4*)(bf + dhalf * 32 + dloc);
#pragma unroll
        for (int i = 0; i < 8; i++)
#pragma unroll
            for (int j = 0; j < 4; j++) {
                float2 v = up2(acc[i][j]);
                po[i][j] = lrelu(v.x + v.y + (&bv.x)[j]);
            }
    }

    // ================ phase B: feat @ wr^T ================
    asm volatile("cp.async.wait_group 0;" ::: "memory");
    __syncthreads();

#pragma unroll
    for (int i = 0; i < 8; i++)
#pragma unroll
        for (int j = 0; j < 4; j++) acc[i][j] = 0ull;

#pragma unroll
    for (int k4 = 0; k4 < 16; k4++) {
        const ulonglong2* wpA = (const ulonglong2*)&g_wq[1][dhalf][2 * k4][dloc];
        const ulonglong2* wpB = (const ulonglong2*)&g_wq[1][dhalf][2 * k4 + 1][dloc];
        ulonglong2 wv0 = wpA[0], wv1 = wpA[1];
        ulonglong2 wv2 = wpB[0], wv3 = wpB[1];
#pragma unroll
        for (int i = 0; i < 8; i++) {
            ulonglong2 xv = *(const ulonglong2*)&sxB[(rw + 16 * i) * 17 + k4];
            acc[i][0] = fma2(xv.x, wv0.x, acc[i][0]);
            acc[i][0] = fma2(xv.y, wv2.x, acc[i][0]);
            acc[i][1] = fma2(xv.x, wv0.y, acc[i][1]);
            acc[i][1] = fma2(xv.y, wv2.y, acc[i][1]);
            acc[i][2] = fma2(xv.x, wv1.x, acc[i][2]);
            acc[i][2] = fma2(xv.y, wv3.x, acc[i][2]);
            acc[i][3] = fma2(xv.x, wv1.y, acc[i][3]);
            acc[i][3] = fma2(xv.y, wv3.y, acc[i][3]);
        }
    }

    // combine + store (float4 per point)
    float4 bv2 = *(const float4*)(br + dhalf * 32 + dloc);
    float4* out4 = (float4*)out;
#pragma unroll
    for (int i = 0; i < 8; i++) {
        int p = rw + 16 * i;
        float4 v;
#pragma unroll
        for (int j = 0; j < 4; j++) {
            float2 w2 = up2(acc[i][j]);
            (&v.x)[j] = po[i][j] + lrelu(w2.x + w2.y + (&bv2.x)[j]);
        }
        out4[(size_t)(r0 + p) * 16 + dhalf * 8 + c] = v;
    }
}

// ---------------------------------------------------------------------------
extern "C" void kernel_launch(void* const* d_in, const int* in_sizes, int n_in,
                              void* d_out, int out_size)
{
    const float* points  = (const float*)d_in[0];
    const float* feats   = (const float*)d_in[1];
    const int*   idx     = (const int*)d_in[2];
    const float* w_init  = (const float*)d_in[3];
    const float* b_init  = (const float*)d_in[4];
    const float* w_lfa1  = (const float*)d_in[5];
    const float* b_lfa1  = (const float*)d_in[6];
    const float* w_lfa2  = (const float*)d_in[7];
    const float* b_lfa2  = (const float*)d_in[8];
    const float* w_final = (const float*)d_in[9];
    const float* b_final = (const float*)d_in[10];
    const float* w_res   = (const float*)d_in[11];
    const float* b_res   = (const float*)d_in[12];
    float* out = (float*)d_out;

    k_packw<<<1, 256>>>(w_final, w_res);
    k_prep_pts<<<NPTS / 256, 256>>>(points);
    k_init<<<NPTS / 16, 256>>>(feats, w_init, b_init);
    k_lfa_geo<<<NPTS / 8, 256>>>(idx, w_lfa1, b_lfa1, w_lfa2, b_lfa2);
    k_gather2<<<NPTS / 8, 256>>>(idx);
    k_final<<<dim3(NPTS / 128, 2), 128>>>(feats, b_final, b_res, out);
}

// round 13
// speedup vs baseline: 1.8138x; 1.5060x over previous
#include <cuda_runtime.h>
#include <cstdint>
#include <math.h>

#define NPTS 131072   // B*N
#define NB   65536    // N (points per batch)
#define KNN  32
#define FD   64

typedef unsigned long long u64;

// Scratch (no allocations allowed)
__device__ float g_x1[NPTS * 16];   // 8 MB   lrelu(feat @ Wi^T)
__device__ float g_x2[NPTS * 32];   // 16 MB  [g1 | f1]
__device__ float g_x3[NPTS * 64];   // 32 MB  [g2 | f2]
__device__ float4 g_pts4[NPTS];     // 2 MB   padded points (x,y,z,0)

// Pre-packed k-pair weights for k_final:
// g_wq[which][dhalf][k2][dloc] = {w[D][2*k2], w[D][2*k2+1]},  D = dhalf*32+dloc
__device__ __align__(16) u64 g_wq[2][2][32][32];

__device__ __forceinline__ float lrelu(float x) { return fmaxf(x, 0.2f * x); }

// ---- packed f32x2 helpers (sm_103a FFMA2 path) ----
__device__ __forceinline__ u64 fma2(u64 a, u64 b, u64 c) {
    u64 r;
    asm("fma.rn.f32x2 %0, %1, %2, %3;" : "=l"(r) : "l"(a), "l"(b), "l"(c));
    return r;
}
__device__ __forceinline__ u64 pk2(float x, float y) {
    u64 r;
    asm("mov.b64 %0, {%1, %2};" : "=l"(r) : "f"(x), "f"(y));
    return r;
}
__device__ __forceinline__ float2 up2(u64 a) {
    float2 v;
    asm("mov.b64 {%0, %1}, %2;" : "=f"(v.x), "=f"(v.y) : "l"(a));
    return v;
}
#define C06_2 0x3F19999A3F19999AULL   // {0.6f, 0.6f}
#define C04_2 0x3ECCCCCD3ECCCCCDULL   // {0.4f, 0.4f}
#define ABSM  0x7FFFFFFF7FFFFFFFULL

// packed lrelu accumulate: acc += lrelu2(s)  where lrelu(x)=0.6x+0.4|x|
__device__ __forceinline__ u64 lrelu_acc2(u64 s, u64 acc) {
    acc = fma2(s, C06_2, acc);
    acc = fma2(s & ABSM, C04_2, acc);
    return acc;
}

__device__ __forceinline__ uint32_t smem_u32(const void* p) {
    uint32_t a;
    asm("{ .reg .u64 t; cvta.to.shared.u64 t, %1; cvt.u32.u64 %0, t; }"
        : "=r"(a) : "l"(p));
    return a;
}
__device__ __forceinline__ void cp16(uint32_t dst, const void* src) {
    asm volatile("cp.async.cg.shared.global [%0], [%1], 16;"
                 :: "r"(dst), "l"(src) : "memory");
}

// ---------------------------------------------------------------------------
// K0a: pack w_final / w_res rows into k-pair u64 chunks (one tiny block).
// ---------------------------------------------------------------------------
__global__ __launch_bounds__(256) void k_packw(
    const float* __restrict__ wf, const float* __restrict__ wr)
{
    int t = threadIdx.x;
    u64* dst = &g_wq[0][0][0][0];
#pragma unroll
    for (int e = t; e < 4096; e += 256) {
        int which = e >> 11;
        int rem   = e & 2047;
        int dh    = rem >> 10;
        int k2    = (rem >> 5) & 31;
        int dloc  = rem & 31;
        const float* src = which ? wr : wf;
        dst[e] = *(const u64*)(src + (size_t)(dh * 32 + dloc) * 64 + k2 * 2);
    }
}

// ---------------------------------------------------------------------------
// K0b: pad points (B,N,3) -> float4 (x,y,z,0): neighbor gather = one LDG.128.
// ---------------------------------------------------------------------------
__global__ __launch_bounds__(256) void k_prep_pts(const float* __restrict__ pts)
{
    int i = blockIdx.x * 256 + threadIdx.x;
    size_t b = (size_t)i * 3;
    g_pts4[i] = make_float4(pts[b], pts[b + 1], pts[b + 2], 0.f);
}

// ---------------------------------------------------------------------------
// K1: x1 = lrelu(features @ w_init^T + b_init)   (NPTS, 16)
// ---------------------------------------------------------------------------
__global__ __launch_bounds__(256) void k_init(
    const float* __restrict__ feat, const float* __restrict__ w,
    const float* __restrict__ b)
{
    __shared__ float4 sf4[256];          // 16 points x 64 feats
    __shared__ float  swt[64 * 16];      // transposed w_init
    __shared__ float  sb[16];
    const float* sf = (const float*)sf4;

    int tid = threadIdx.x;
    int fb  = blockIdx.x * 16;

    const float4* f4 = (const float4*)feat + (size_t)fb * 16;
    sf4[tid] = f4[tid];

#pragma unroll
    for (int e = tid; e < 1024; e += 256) {
        int d = e >> 6, i = e & 63;
        swt[i * 16 + d] = w[e];
    }
    if (tid < 16) sb[tid] = b[tid];
    __syncthreads();

    int p = tid >> 4, d = tid & 15;
    float acc = sb[d];
#pragma unroll
    for (int i = 0; i < 64; i++)
        acc = fmaf(sf[p * 64 + i], swt[i * 16 + d], acc);

    g_x1[(size_t)fb * 16 + tid] = lrelu(acc);
}

// ---------------------------------------------------------------------------
// K2: fused geo-MLPs of lfa1 + lfa2 (shared geometry) + x1 gather-mean.
// One warp per point. ALU diet: no SELs (half-dependent operands read via
// LDS.64 with immediate offsets off a per-lane base), f1 index pair via one
// int2 LDS, hoisted gather base. Dual accumulator chains.
// ---------------------------------------------------------------------------
__global__ __launch_bounds__(256) void k_lfa_geo(
    const int* __restrict__ idx,
    const float* __restrict__ w1, const float* __restrict__ b1,
    const float* __restrict__ w2, const float* __restrict__ b2)
{
    __shared__ __align__(16) float sgx[8][32];
    __shared__ __align__(16) float sgy[8][32];
    __shared__ __align__(16) float sgz[8][32];
    __shared__ __align__(16) float sgd[8][32];
    __shared__ __align__(16) int sidx[8][32];

    int lane = threadIdx.x & 31;
    int wid  = threadIdx.x >> 5;
    int r    = blockIdx.x * 8 + wid;
    int base = (r >= NB) ? NB : 0;       // batch row base

    int ij = idx[(size_t)r * KNN + lane];
    sidx[wid][lane] = ij;

    float4 cp = g_pts4[r];                       // broadcast LDG.128
    float4 np = g_pts4[base + ij];               // scattered LDG.128

    float rx = cp.x - np.x, ry = cp.y - np.y, rz = cp.z - np.z;
    float dist = sqrtf(fmaf(rx, rx, fmaf(ry, ry, rz * rz)));
    sgx[wid][lane] = rx;
    sgy[wid][lane] = ry;
    sgz[wid][lane] = rz;
    sgd[wid][lane] = dist;

    // per-lane weight rows, packed {w,w}
    float4 w2r = ((const float4*)w2)[lane];
    u64 w2xx = pk2(w2r.x, w2r.x), w2yy = pk2(w2r.y, w2r.y);
    u64 w2zz = pk2(w2r.z, w2r.z), w2ww = pk2(w2r.w, w2r.w);
    u64 bias2 = pk2(b2[lane], b2[lane]);

    int dlo = lane & 15;
    int h2  = (lane >> 4) * 2;           // 0 or 2: half-dependent pair offset
    float4 w1r = ((const float4*)w1)[dlo];
    u64 w1xx = pk2(w1r.x, w1r.x), w1yy = pk2(w1r.y, w1r.y);
    u64 w1zz = pk2(w1r.z, w1r.z), w1ww = pk2(w1r.w, w1r.w);
    u64 bias1 = pk2(b1[dlo], b1[dlo]);

    // half-dependent base pointers (2*h folds in here; loop offsets immediate)
    const float* bx = &sgx[wid][h2];
    const float* by = &sgy[wid][h2];
    const float* bz = &sgz[wid][h2];
    const float* bd = &sgd[wid][h2];
    const int*   bi = &sidx[wid][h2];
    const float* x1b = g_x1 + (size_t)base * 16 + dlo;   // f1 gather base

    __syncwarp();

    u64 ag2a = 0, ag2b = 0, ag1a = 0, ag1b = 0;
    float af1a = 0.f, af1b = 0.f;

#pragma unroll
    for (int it = 0; it < 8; it++) {
        int j0 = it * 4;
        // LDS.128 broadcast: two packed neighbor-pairs per component
        ulonglong2 gx = *(const ulonglong2*)&sgx[wid][j0];
        ulonglong2 gy = *(const ulonglong2*)&sgy[wid][j0];
        ulonglong2 gz = *(const ulonglong2*)&sgz[wid][j0];
        ulonglong2 gd = *(const ulonglong2*)&sgd[wid][j0];

        // ---- g2: all 32 lanes (d = lane), both pairs (dual chains) ----
        u64 s0 = fma2(gx.x, w2xx, bias2);
        s0 = fma2(gy.x, w2yy, s0);
        s0 = fma2(gz.x, w2zz, s0);
        s0 = fma2(gd.x, w2ww, s0);
        ag2a = lrelu_acc2(s0, ag2a);

        u64 s1 = fma2(gx.y, w2xx, bias2);
        s1 = fma2(gy.y, w2yy, s1);
        s1 = fma2(gz.y, w2zz, s1);
        s1 = fma2(gd.y, w2ww, s1);
        ag2b = lrelu_acc2(s1, ag2b);

        // ---- g1: half-dependent pair via LDS.64 at immediate offsets ----
        u64 qx = *(const u64*)(bx + j0);
        u64 qy = *(const u64*)(by + j0);
        u64 qz = *(const u64*)(bz + j0);
        u64 qd = *(const u64*)(bd + j0);
        u64 t = fma2(qx, w1xx, bias1);
        t = fma2(qy, w1yy, t);
        t = fma2(qz, w1zz, t);
        t = fma2(qd, w1ww, t);
        if (it & 1) ag1b = lrelu_acc2(t, ag1b);
        else        ag1a = lrelu_acc2(t, ag1a);

        // ---- f1 gather: index pair via one int2 LDS ----
        int2 nn = *(const int2*)(bi + j0);
        af1a += x1b[(size_t)nn.x * 16];
        af1b += x1b[(size_t)nn.y * 16];
    }

    const float inv = 1.0f / 32.0f;

    float2 a2a = up2(ag2a);
    float2 a2b = up2(ag2b);
    g_x3[(size_t)r * 64 + lane] = (a2a.x + a2a.y + a2b.x + a2b.y) * inv;

    // fold lane-halves for g1 / f1
    float af1 = af1a + af1b;
    u64 ag1;
    {
        float2 pa = up2(ag1a), pb = up2(ag1b);
        ag1 = pk2(pa.x + pb.x, pa.y + pb.y);
    }
    u64 ag1o = __shfl_down_sync(0xffffffffu, ag1, 16);
    float af1o = __shfl_down_sync(0xffffffffu, af1, 16);
    if (lane < 16) {
        float2 a1  = up2(ag1);
        float2 a1o = up2(ag1o);
        g_x2[(size_t)r * 32 + lane]      = (a1.x + a1.y + a1o.x + a1o.y) * inv;
        g_x2[(size_t)r * 32 + 16 + lane] = (af1 + af1o) * inv;
    }
}

// ---------------------------------------------------------------------------
// K3a: f2[d] = mean_k x2[nbr_k][d]  (32 dims)  -> g_x3[r][32:64]
// At the LTS chip throughput cap (~11 TB/s of L2 gather) — do not touch.
// ---------------------------------------------------------------------------
__global__ __launch_bounds__(256) void k_gather2(const int* __restrict__ idx)
{
    __shared__ int sidx[8][32];
    int lane = threadIdx.x & 31;
    int wid  = threadIdx.x >> 5;
    int r    = blockIdx.x * 8 + wid;
    int base = (r >= NB) ? NB : 0;

    sidx[wid][lane] = idx[(size_t)r * KNN + lane];
    __syncwarp();

    float acc = 0.f;
#pragma unroll
    for (int j = 0; j < 32; j++) {
        int nr = sidx[wid][j];
        acc += g_x2[(size_t)(base + nr) * 32 + lane];  // coalesced 128B
    }
    g_x3[(size_t)r * 64 + 32 + lane] = acc * (1.0f / 32.0f);
}

// ---------------------------------------------------------------------------
// K3b: out = lrelu(x3 @ wf^T + bf) + lrelu(feat @ wr^T + br)
// Two-phase, cp.async double-buffered. w via L1-resident LDG.128 from g_wq,
// packed FFMA2, zero packing movs. 128 thr, 8 pts x 4 outs.
// ---------------------------------------------------------------------------
__global__ __launch_bounds__(128) void k_final(
    const float* __restrict__ feat,
    const float* __restrict__ bf, const float* __restrict__ br,
    float* __restrict__ out)
{
    __shared__ float4 sxA[128 * 17];            // x3 tile, padded
    __shared__ float4 sxB[128 * 17];            // feat tile, padded

    int tid   = threadIdx.x;
    int dhalf = blockIdx.y;                     // 0: outs 0-31, 1: outs 32-63
    int r0    = blockIdx.x * 128;
    int c     = tid & 7;                        // out group: local d = c*4..c*4+3
    int rw    = tid >> 3;                       // 0..15; points p = rw + 16*i
    int dloc  = c * 4;

    // ---- stream both tiles in via cp.async (B overlaps A's compute) ----
    {
        uint32_t sA = smem_u32(sxA);
        uint32_t sB = smem_u32(sxB);
        const float4* srcA = (const float4*)g_x3 + (size_t)r0 * 16;
        const float4* srcB = (const float4*)feat + (size_t)r0 * 16;
#pragma unroll
        for (int e = tid; e < 2048; e += 128) {
            int p = e >> 4, k4 = e & 15;
            cp16(sA + (uint32_t)(p * 17 + k4) * 16, srcA + e);
        }
        asm volatile("cp.async.commit_group;" ::: "memory");
#pragma unroll
        for (int e = tid; e < 2048; e += 128) {
            int p = e >> 4, k4 = e & 15;
            cp16(sB + (uint32_t)(p * 17 + k4) * 16, srcB + e);
        }
        asm volatile("cp.async.commit_group;" ::: "memory");
    }

    u64 acc[8][4];
    float po[8][4];

    // ================ phase A: x3 @ wf^T ================
    asm volatile("cp.async.wait_group 1;" ::: "memory");
    __syncthreads();

#pragma unroll
    for (int i = 0; i < 8; i++)
#pragma unroll
        for (int j = 0; j < 4; j++) acc[i][j] = 0ull;

#pragma unroll
    for (int k4 = 0; k4 < 16; k4++) {
        const ulonglong2* wpA = (const ulonglong2*)&g_wq[0][dhalf][2 * k4][dloc];
        const ulonglong2* wpB = (const ulonglong2*)&g_wq[0][dhalf][2 * k4 + 1][dloc];
        ulonglong2 wv0 = wpA[0], wv1 = wpA[1];
        ulonglong2 wv2 = wpB[0], wv3 = wpB[1];
#pragma unroll
        for (int i = 0; i < 8; i++) {
            ulonglong2 xv = *(const ulonglong2*)&sxA[(rw + 16 * i) * 17 + k4];
            acc[i][0] = fma2(xv.x, wv0.x, acc[i][0]);
            acc[i][0] = fma2(xv.y, wv2.x, acc[i][0]);
            acc[i][1] = fma2(xv.x, wv0.y, acc[i][1]);
            acc[i][1] = fma2(xv.y, wv2.y, acc[i][1]);
            acc[i][2] = fma2(xv.x, wv1.x, acc[i][2]);
            acc[i][2] = fma2(xv.y, wv3.x, acc[i][2]);
            acc[i][3] = fma2(xv.x, wv1.y, acc[i][3]);
            acc[i][3] = fma2(xv.y, wv3.y, acc[i][3]);
        }
    }

    {
        float4 bv = *(const float4*)(bf + dhalf * 32 + dloc);
#pragma unroll
        for (int i = 0; i < 8; i++)
#pragma unroll
            for (int j = 0; j < 4; j++) {
                float2 v = up2(acc[i][j]);
                po[i][j] = lrelu(v.x + v.y + (&bv.x)[j]);
            }
    }

    // ================ phase B: feat @ wr^T ================
    asm volatile("cp.async.wait_group 0;" ::: "memory");
    __syncthreads();

#pragma unroll
    for (int i = 0; i < 8; i++)
#pragma unroll
        for (int j = 0; j < 4; j++) acc[i][j] = 0ull;

#pragma unroll
    for (int k4 = 0; k4 < 16; k4++) {
        const ulonglong2* wpA = (const ulonglong2*)&g_wq[1][dhalf][2 * k4][dloc];
        const ulonglong2* wpB = (const ulonglong2*)&g_wq[1][dhalf][2 * k4 + 1][dloc];
        ulonglong2 wv0 = wpA[0], wv1 = wpA[1];
        ulonglong2 wv2 = wpB[0], wv3 = wpB[1];
#pragma unroll
        for (int i = 0; i < 8; i++) {
            ulonglong2 xv = *(const ulonglong2*)&sxB[(rw + 16 * i) * 17 + k4];
            acc[i][0] = fma2(xv.x, wv0.x, acc[i][0]);
            acc[i][0] = fma2(xv.y, wv2.x, acc[i][0]);
            acc[i][1] = fma2(xv.x, wv0.y, acc[i][1]);
            acc[i][1] = fma2(xv.y, wv2.y, acc[i][1]);
            acc[i][2] = fma2(xv.x, wv1.x, acc[i][2]);
            acc[i][2] = fma2(xv.y, wv3.x, acc[i][2]);
            acc[i][3] = fma2(xv.x, wv1.y, acc[i][3]);
            acc[i][3] = fma2(xv.y, wv3.y, acc[i][3]);
        }
    }

    // combine + store (float4 per point)
    float4 bv2 = *(const float4*)(br + dhalf * 32 + dloc);
    float4* out4 = (float4*)out;
#pragma unroll
    for (int i = 0; i < 8; i++) {
        int p = rw + 16 * i;
        float4 v;
#pragma unroll
        for (int j = 0; j < 4; j++) {
            float2 w2 = up2(acc[i][j]);
            (&v.x)[j] = po[i][j] + lrelu(w2.x + w2.y + (&bv2.x)[j]);
        }
        out4[(size_t)(r0 + p) * 16 + dhalf * 8 + c] = v;
    }
}

// ---------------------------------------------------------------------------
extern "C" void kernel_launch(void* const* d_in, const int* in_sizes, int n_in,
                              void* d_out, int out_size)
{
    const float* points  = (const float*)d_in[0];
    const float* feats   = (const float*)d_in[1];
    const int*   idx     = (const int*)d_in[2];
    const float* w_init  = (const float*)d_in[3];
    const float* b_init  = (const float*)d_in[4];
    const float* w_lfa1  = (const float*)d_in[5];
    const float* b_lfa1  = (const float*)d_in[6];
    const float* w_lfa2  = (const float*)d_in[7];
    const float* b_lfa2  = (const float*)d_in[8];
    const float* w_final = (const float*)d_in[9];
    const float* b_final = (const float*)d_in[10];
    const float* w_res   = (const float*)d_in[11];
    const float* b_res   = (const float*)d_in[12];
    float* out = (float*)d_out;

    k_packw<<<1, 256>>>(w_final, w_res);
    k_prep_pts<<<NPTS / 256, 256>>>(points);
    k_init<<<NPTS / 16, 256>>>(feats, w_init, b_init);
    k_lfa_geo<<<NPTS / 8, 256>>>(idx, w_lfa1, b_lfa1, w_lfa2, b_lfa2);
    k_gather2<<<NPTS / 8, 256>>>(idx);
    k_final<<<dim3(NPTS / 128, 2), 128>>>(feats, b_final, b_res, out);
}